// round 8
// baseline (speedup 1.0000x reference)
#include <cuda_runtime.h>
#include <math.h>

#define BB 64
#define TT 512
#define HH 512
#define GG 2048          // 4*H
#define RECBLK 128
#define RECTHR 256

// ---- static device scratch (no cudaMalloc allowed) ----
__device__ float g_G[67108864];    // G^T: [col 0..2048)[r=t*64+b 0..32768)  (268 MB)
__device__ float g_H0T[16777216];  // layer-0 output archive: [u][r]          (64 MB)
__device__ float g_h[65536];       // h state double buffer: 2 x [b][u]
__device__ unsigned g_leaf[8 * 64];  // 8 leaf counters, 256B apart
__device__ unsigned g_root;
__device__ unsigned g_gen;

// ---- L2-scope sync primitives (no L1 flush) ----
__device__ __forceinline__ unsigned atomAddRel(unsigned* p) {
    unsigned old;
    asm volatile("atom.release.gpu.global.add.u32 %0, [%1], 1;"
                 : "=r"(old) : "l"(p) : "memory");
    return old;
}
__device__ __forceinline__ unsigned ldAcq(const unsigned* p) {
    unsigned v;
    asm volatile("ld.acquire.gpu.global.u32 %0, [%1];"
                 : "=r"(v) : "l"(p) : "memory");
    return v;
}
__device__ __forceinline__ void stRel(unsigned* p, unsigned v) {
    asm volatile("st.release.gpu.global.u32 [%0], %1;"
                 :: "l"(p), "r"(v) : "memory");
}

// ---- monotonic 2-level grid barrier (replay-safe: no resets) ----
__device__ __forceinline__ void gridBarrier() {
    __syncthreads();
    if (threadIdx.x == 0) {
        unsigned g = ldAcq(&g_gen);
        unsigned leaf = (blockIdx.x >> 4) << 6;
        unsigned old = atomAddRel(&g_leaf[leaf]);
        if (old == g * 16u + 15u) {
            unsigned o2 = atomAddRel(&g_root);
            if (o2 == g * 8u + 7u) {
                stRel(&g_gen, g + 1u);
            } else {
                while (ldAcq(&g_gen) == g) { }
            }
        } else {
            while (ldAcq(&g_gen) == g) { }
        }
    }
    __syncthreads();
}

__device__ __forceinline__ float sigmoidf_(float x) {
    return 1.0f / (1.0f + __expf(-x));
}

__device__ __forceinline__ unsigned smem_u32(const void* p) {
    unsigned a;
    asm("{ .reg .u64 t; cvta.to.shared.u64 t, %1; cvt.u32.u64 %0, t; }"
        : "=r"(a) : "l"(p));
    return a;
}

// ============================================================
// Precompute GEMM (transposed output), FFMA2 inner loop:
//   Gt[col][r] = W[col][:] . Xrow(r)[:] + bih[col] + bhh[col]
//   M = col = 2048, N = r = 32768, K = 512.
// ============================================================
__global__ void __launch_bounds__(256) lstm_pregemm(
    const float* __restrict__ xin,
    const float* __restrict__ Wih,
    const float* __restrict__ bih,
    const float* __restrict__ bhh,
    int layer0)
{
    __shared__ __align__(16) float As[16][128];   // [k][m=col]
    __shared__ __align__(16) float Bs[16][128];   // [k][n=r]
    const int tid = threadIdx.x;
    const int rblk = blockIdx.x * 128;   // n
    const int mblk = blockIdx.y * 128;   // m (col)
    const int nx = tid & 15;
    const int mx = tid >> 4;

    unsigned long long acc[8][4];
    #pragma unroll
    for (int i = 0; i < 8; ++i)
        #pragma unroll
        for (int j = 0; j < 4; ++j) acc[i][j] = 0ull;

    const unsigned bsBase = smem_u32(Bs) + (unsigned)nx * 32u;

    for (int kc = 0; kc < 512; kc += 16) {
        #pragma unroll
        for (int jj = 0; jj < 2; ++jj) {
            int e = tid + jj * 256;
            int m = e >> 2;
            int kq = e & 3;
            float4 v = *(const float4*)(Wih + (size_t)(mblk + m) * 512 + kc + kq * 4);
            As[kq*4+0][m] = v.x; As[kq*4+1][m] = v.y;
            As[kq*4+2][m] = v.z; As[kq*4+3][m] = v.w;
        }
        if (layer0) {
            #pragma unroll
            for (int jj = 0; jj < 2; ++jj) {
                int e = tid + jj * 256;
                int n = e >> 2;
                int kq = e & 3;
                int r = rblk + n;
                const float* src = xin + (size_t)(((r & 63) << 9) + (r >> 6)) * 512;
                float4 v = *(const float4*)(src + kc + kq * 4);
                Bs[kq*4+0][n] = v.x; Bs[kq*4+1][n] = v.y;
                Bs[kq*4+2][n] = v.z; Bs[kq*4+3][n] = v.w;
            }
        } else {
            #pragma unroll
            for (int jj = 0; jj < 2; ++jj) {
                int e = tid + jj * 256;
                int k = e >> 5;
                int nq = e & 31;
                *(float4*)&Bs[k][nq * 4] =
                    *(const float4*)(g_H0T + (size_t)(kc + k) * 32768 + rblk + nq * 4);
            }
        }
        __syncthreads();
        #pragma unroll
        for (int k = 0; k < 16; ++k) {
            float a[8];
            *(float4*)(a)     = *(const float4*)&As[k][mx * 8];
            *(float4*)(a + 4) = *(const float4*)&As[k][mx * 8 + 4];
            unsigned long long b0, b1, b2, b3;
            unsigned ba = bsBase + (unsigned)k * 512u;
            asm("ld.shared.v2.u64 {%0,%1},[%2];" : "=l"(b0), "=l"(b1) : "r"(ba));
            asm("ld.shared.v2.u64 {%0,%1},[%2];" : "=l"(b2), "=l"(b3) : "r"(ba + 16u));
            #pragma unroll
            for (int i = 0; i < 8; ++i) {
                unsigned long long hh;
                asm("mov.b64 %0,{%1,%2};" : "=l"(hh) : "f"(a[i]), "f"(a[i]));
                asm("fma.rn.f32x2 %0,%1,%2,%0;" : "+l"(acc[i][0]) : "l"(hh), "l"(b0));
                asm("fma.rn.f32x2 %0,%1,%2,%0;" : "+l"(acc[i][1]) : "l"(hh), "l"(b1));
                asm("fma.rn.f32x2 %0,%1,%2,%0;" : "+l"(acc[i][2]) : "l"(hh), "l"(b2));
                asm("fma.rn.f32x2 %0,%1,%2,%0;" : "+l"(acc[i][3]) : "l"(hh), "l"(b3));
            }
        }
        __syncthreads();
    }

    #pragma unroll
    for (int i = 0; i < 8; ++i) {
        int col = mblk + mx * 8 + i;
        float bsum = bih[col] + bhh[col];
        float f[8];
        #pragma unroll
        for (int j = 0; j < 4; ++j)
            asm("mov.b64 {%0,%1},%2;" : "=f"(f[2*j]), "=f"(f[2*j+1]) : "l"(acc[i][j]));
        float* dst = g_G + (size_t)col * 32768 + rblk + nx * 8;
        float4 v0 = make_float4(f[0]+bsum, f[1]+bsum, f[2]+bsum, f[3]+bsum);
        float4 v1 = make_float4(f[4]+bsum, f[5]+bsum, f[6]+bsum, f[7]+bsum);
        *(float4*)dst = v0;
        *(float4*)(dst + 4) = v1;
    }
}

// ============================================================
// Persistent recurrent kernel v4: 128 CTAs x 256 threads.
// CTA j owns units u0=4j..4j+3 (16 gate-cols), all 64 b.
// Thread (bG = w*8 + (l>>2), q = l&3): 16 cols over k in [q*128,(q+1)*128)
//  -> 8 independent FFMA2 chains, 4x less h traffic, shfl-xor split-K reduce.
// One grid barrier per step; c state in registers; h via L2 (ldcg/stcg).
// ============================================================
__global__ void __launch_bounds__(RECTHR, 1) lstm_recurrent(
    const float* __restrict__ Whh,
    const float* __restrict__ h0,
    const float* __restrict__ c0,
    float* __restrict__ outSeq,   // layer1: [b][t][u]; layer0: null (writes g_H0T)
    float* __restrict__ hfin,
    float* __restrict__ cfin,
    int layer1)
{
    __shared__ __align__(16) float Wt[512 * 16];   // [k][16]  c = g*4 + j
    __shared__ float gsum[64 * 17];

    const int tid = threadIdx.x;
    const int bid = blockIdx.x;
    const int u0  = bid * 4;
    const int w   = tid >> 5;
    const int l   = tid & 31;
    const int bG  = w * 8 + (l >> 2);    // GEMM batch row
    const int q   = l & 3;               // k-split quarter
    const int bC  = tid & 63;            // cell batch
    const int uu  = tid >> 6;            // cell unit offset

    // persistent weight tile: Wt[k][c], c = g*4+j <- Whh[g*512 + u0 + j][k]
    for (int e = tid; e < 16 * 512; e += RECTHR) {
        int c = e >> 9;
        int k = e & 511;
        int g = c >> 2, j = c & 3;
        Wt[k * 16 + c] = Whh[(size_t)(g * 512 + u0 + j) * 512 + k];
    }

    // init state
    {
        int idx = bid * RECTHR + tid;
        __stcg(&g_h[idx], h0[idx]);
    }
    float c_reg = c0[bC * HH + u0 + uu];

    const unsigned wsmBase = smem_u32(Wt) + (unsigned)q * 8192u;  // q*128 k rows * 64B

    gridBarrier();

    for (int t = 0; t < TT; ++t) {
        const float* hRead = g_h + (t & 1) * 32768;
        float* hWrite      = g_h + ((t + 1) & 1) * 32768;
        const float4* hsrc = (const float4*)(hRead + bG * 512 + q * 128);

        unsigned long long acc[8];
        #pragma unroll
        for (int j = 0; j < 8; ++j) acc[j] = 0ull;

        float4 A[4], Bf[4];
        auto ldc = [&](float4 (&d)[4], int ch) {
            #pragma unroll
            for (int i = 0; i < 4; ++i) d[i] = __ldcg(hsrc + ch * 4 + i);
        };
        auto comp = [&](const float4 (&hb)[4], int ch) {
            unsigned wb = wsmBase + (unsigned)ch * 1024u;
            #pragma unroll
            for (int i = 0; i < 4; ++i) {
                float4 hv = hb[i];
                #pragma unroll
                for (int kk = 0; kk < 4; ++kk) {
                    float h = (&hv.x)[kk];
                    unsigned long long hh, w0, w1, w2, w3, w4, w5, w6, w7;
                    asm("mov.b64 %0,{%1,%2};" : "=l"(hh) : "f"(h), "f"(h));
                    unsigned a = wb + (unsigned)((i * 4 + kk) * 64);
                    asm("ld.shared.v2.u64 {%0,%1},[%2];" : "=l"(w0), "=l"(w1) : "r"(a));
                    asm("ld.shared.v2.u64 {%0,%1},[%2];" : "=l"(w2), "=l"(w3) : "r"(a + 16u));
                    asm("ld.shared.v2.u64 {%0,%1},[%2];" : "=l"(w4), "=l"(w5) : "r"(a + 32u));
                    asm("ld.shared.v2.u64 {%0,%1},[%2];" : "=l"(w6), "=l"(w7) : "r"(a + 48u));
                    asm("fma.rn.f32x2 %0,%1,%2,%0;" : "+l"(acc[0]) : "l"(hh), "l"(w0));
                    asm("fma.rn.f32x2 %0,%1,%2,%0;" : "+l"(acc[1]) : "l"(hh), "l"(w1));
                    asm("fma.rn.f32x2 %0,%1,%2,%0;" : "+l"(acc[2]) : "l"(hh), "l"(w2));
                    asm("fma.rn.f32x2 %0,%1,%2,%0;" : "+l"(acc[3]) : "l"(hh), "l"(w3));
                    asm("fma.rn.f32x2 %0,%1,%2,%0;" : "+l"(acc[4]) : "l"(hh), "l"(w4));
                    asm("fma.rn.f32x2 %0,%1,%2,%0;" : "+l"(acc[5]) : "l"(hh), "l"(w5));
                    asm("fma.rn.f32x2 %0,%1,%2,%0;" : "+l"(acc[6]) : "l"(hh), "l"(w6));
                    asm("fma.rn.f32x2 %0,%1,%2,%0;" : "+l"(acc[7]) : "l"(hh), "l"(w7));
                }
            }
        };

        ldc(A, 0); ldc(Bf, 1);
        comp(A, 0); ldc(A, 2);
        comp(Bf, 1); ldc(Bf, 3);
        comp(A, 2); ldc(A, 4);
        comp(Bf, 3); ldc(Bf, 5);
        comp(A, 4); ldc(A, 6);
        comp(Bf, 5); ldc(Bf, 7);
        comp(A, 6); comp(Bf, 7);

        // split-K reduce over the 4 lanes of the quad (q = l&3)
        float s[16];
        #pragma unroll
        for (int j = 0; j < 8; ++j)
            asm("mov.b64 {%0,%1},%2;" : "=f"(s[2*j]), "=f"(s[2*j+1]) : "l"(acc[j]));
        #pragma unroll
        for (int j = 0; j < 16; ++j) {
            s[j] += __shfl_xor_sync(0xffffffffu, s[j], 1);
            s[j] += __shfl_xor_sync(0xffffffffu, s[j], 2);
        }
        // lane q writes its quarter of the 16 columns
        {
            float* gs = gsum + bG * 17 + q * 4;
            gs[0] = s[q*4+0]; gs[1] = s[q*4+1]; gs[2] = s[q*4+2]; gs[3] = s[q*4+3];
        }
        __syncthreads();

        // ---- cell update (thread owns (bC, u0+uu); c in register) ----
        {
            float sg[4];
            #pragma unroll
            for (int g = 0; g < 4; ++g) {
                float recur = gsum[bC * 17 + g * 4 + uu];
                float pre = __ldcs(g_G + (size_t)(g * 512 + u0 + uu) * 32768
                                       + (size_t)t * 64 + bC);
                sg[g] = recur + pre;
            }
            float iv = sigmoidf_(sg[0]);
            float fv = sigmoidf_(sg[1]);
            float gv = tanhf(sg[2]);
            float ov = sigmoidf_(sg[3]);
            c_reg = fv * c_reg + iv * gv;
            float hv = ov * tanhf(c_reg);

            __stcg(&hWrite[bC * HH + u0 + uu], hv);
            if (layer1) outSeq[((size_t)bC * TT + t) * HH + u0 + uu] = hv;
            else        __stcg(&g_H0T[(size_t)(u0 + uu) * 32768 + (size_t)t * 64 + bC], hv);
            if (t == TT - 1) {
                hfin[bC * HH + u0 + uu] = hv;
                cfin[bC * HH + u0 + uu] = c_reg;
            }
        }
        gridBarrier();
    }
}

// ============================================================
// kernel_launch: 4 graph-capturable launches.
// Output: out [B,T,H] ++ h_fin [2,B,H] ++ c_fin [2,B,H]
// ============================================================
extern "C" void kernel_launch(void* const* d_in, const int* in_sizes, int n_in,
                              void* d_out, int out_size)
{
    (void)in_sizes; (void)n_in; (void)out_size;
    const float* x   = (const float*)d_in[0];
    const float* h0  = (const float*)d_in[1];
    const float* c0  = (const float*)d_in[2];
    const float* Wih = (const float*)d_in[3];
    const float* Whh = (const float*)d_in[4];
    const float* bih = (const float*)d_in[5];
    const float* bhh = (const float*)d_in[6];
    float* out  = (float*)d_out;
    float* hfin = out + (size_t)BB * TT * HH;
    float* cfin = hfin + 2 * BB * HH;

    dim3 pgrid(32768 / 128, GG / 128);   // (256, 16)

    // layer 0
    lstm_pregemm<<<pgrid, 256>>>(x, Wih, bih, bhh, 1);
    lstm_recurrent<<<RECBLK, RECTHR>>>(Whh, h0, c0, nullptr, hfin, cfin, 0);
    // layer 1 (input GEMM reads g_H0T directly)
    lstm_pregemm<<<pgrid, 256>>>(x, Wih + (size_t)GG * 512, bih + GG, bhh + GG, 0);
    lstm_recurrent<<<RECBLK, RECTHR>>>(Whh + (size_t)GG * 512,
                                       h0 + BB * HH, c0 + BB * HH,
                                       out, hfin + BB * HH, cfin + BB * HH, 1);
}

// round 12
// speedup vs baseline: 3.5566x; 3.5566x over previous
#include <cuda_runtime.h>
#include <math.h>

#define BB 64
#define TT 512
#define HH 512
#define GG 2048          // 4*H
#define RECBLK 128
#define RECTHR 256

// ---- static device scratch (no cudaMalloc allowed) ----
__device__ float g_G[67108864];    // G^T: [col 0..2048)[r=t*64+b 0..32768)  (268 MB)
__device__ float g_H0T[16777216];  // layer-0 output archive: [u][r]          (64 MB)
__device__ float g_h[65536];       // h state double buffer: 2 x [b][u]
__device__ unsigned g_leaf[8 * 64];  // 8 leaf counters, 256B apart
__device__ unsigned g_root;
__device__ unsigned g_gen;

// ---- L2-scope sync primitives (no L1 flush) ----
__device__ __forceinline__ unsigned atomAddRel(unsigned* p) {
    unsigned old;
    asm volatile("atom.release.gpu.global.add.u32 %0, [%1], 1;"
                 : "=r"(old) : "l"(p) : "memory");
    return old;
}
__device__ __forceinline__ unsigned ldAcq(const unsigned* p) {
    unsigned v;
    asm volatile("ld.acquire.gpu.global.u32 %0, [%1];"
                 : "=r"(v) : "l"(p) : "memory");
    return v;
}
__device__ __forceinline__ void stRel(unsigned* p, unsigned v) {
    asm volatile("st.release.gpu.global.u32 [%0], %1;"
                 :: "l"(p), "r"(v) : "memory");
}

// ---- monotonic 2-level grid barrier (replay-safe: no resets) ----
__device__ __forceinline__ void gridBarrier() {
    __syncthreads();
    if (threadIdx.x == 0) {
        unsigned g = ldAcq(&g_gen);
        unsigned leaf = (blockIdx.x >> 4) << 6;
        unsigned old = atomAddRel(&g_leaf[leaf]);
        if (old == g * 16u + 15u) {
            unsigned o2 = atomAddRel(&g_root);
            if (o2 == g * 8u + 7u) {
                stRel(&g_gen, g + 1u);
            } else {
                while (ldAcq(&g_gen) == g) { }
            }
        } else {
            while (ldAcq(&g_gen) == g) { }
        }
    }
    __syncthreads();
}

__device__ __forceinline__ float sigmoidf_(float x) {
    return 1.0f / (1.0f + __expf(-x));
}

__device__ __forceinline__ unsigned smem_u32(const void* p) {
    unsigned a;
    asm("{ .reg .u64 t; cvta.to.shared.u64 t, %1; cvt.u32.u64 %0, t; }"
        : "=r"(a) : "l"(p));
    return a;
}

// ============================================================
// Precompute GEMM (transposed output), FFMA2 inner loop:
//   Gt[col][r] = W[col][:] . Xrow(r)[:] + bih[col] + bhh[col]
//   M = col = 2048, N = r = 32768, K = 512.
// ============================================================
__global__ void __launch_bounds__(256) lstm_pregemm(
    const float* __restrict__ xin,
    const float* __restrict__ Wih,
    const float* __restrict__ bih,
    const float* __restrict__ bhh,
    int layer0)
{
    __shared__ __align__(16) float As[16][128];   // [k][m=col]
    __shared__ __align__(16) float Bs[16][128];   // [k][n=r]
    const int tid = threadIdx.x;
    const int rblk = blockIdx.x * 128;   // n
    const int mblk = blockIdx.y * 128;   // m (col)
    const int nx = tid & 15;
    const int mx = tid >> 4;

    unsigned long long acc[8][4];
    #pragma unroll
    for (int i = 0; i < 8; ++i)
        #pragma unroll
        for (int j = 0; j < 4; ++j) acc[i][j] = 0ull;

    const unsigned bsBase = smem_u32(Bs) + (unsigned)nx * 32u;

    for (int kc = 0; kc < 512; kc += 16) {
        #pragma unroll
        for (int jj = 0; jj < 2; ++jj) {
            int e = tid + jj * 256;
            int m = e >> 2;
            int kq = e & 3;
            float4 v = *(const float4*)(Wih + (size_t)(mblk + m) * 512 + kc + kq * 4);
            As[kq*4+0][m] = v.x; As[kq*4+1][m] = v.y;
            As[kq*4+2][m] = v.z; As[kq*4+3][m] = v.w;
        }
        if (layer0) {
            #pragma unroll
            for (int jj = 0; jj < 2; ++jj) {
                int e = tid + jj * 256;
                int n = e >> 2;
                int kq = e & 3;
                int r = rblk + n;
                const float* src = xin + (size_t)(((r & 63) << 9) + (r >> 6)) * 512;
                float4 v = *(const float4*)(src + kc + kq * 4);
                Bs[kq*4+0][n] = v.x; Bs[kq*4+1][n] = v.y;
                Bs[kq*4+2][n] = v.z; Bs[kq*4+3][n] = v.w;
            }
        } else {
            #pragma unroll
            for (int jj = 0; jj < 2; ++jj) {
                int e = tid + jj * 256;
                int k = e >> 5;
                int nq = e & 31;
                *(float4*)&Bs[k][nq * 4] =
                    *(const float4*)(g_H0T + (size_t)(kc + k) * 32768 + rblk + nq * 4);
            }
        }
        __syncthreads();
        #pragma unroll
        for (int k = 0; k < 16; ++k) {
            float a[8];
            *(float4*)(a)     = *(const float4*)&As[k][mx * 8];
            *(float4*)(a + 4) = *(const float4*)&As[k][mx * 8 + 4];
            unsigned long long b0, b1, b2, b3;
            unsigned ba = bsBase + (unsigned)k * 512u;
            asm("ld.shared.v2.u64 {%0,%1},[%2];" : "=l"(b0), "=l"(b1) : "r"(ba));
            asm("ld.shared.v2.u64 {%0,%1},[%2];" : "=l"(b2), "=l"(b3) : "r"(ba + 16u));
            #pragma unroll
            for (int i = 0; i < 8; ++i) {
                unsigned long long hh;
                asm("mov.b64 %0,{%1,%2};" : "=l"(hh) : "f"(a[i]), "f"(a[i]));
                asm("fma.rn.f32x2 %0,%1,%2,%0;" : "+l"(acc[i][0]) : "l"(hh), "l"(b0));
                asm("fma.rn.f32x2 %0,%1,%2,%0;" : "+l"(acc[i][1]) : "l"(hh), "l"(b1));
                asm("fma.rn.f32x2 %0,%1,%2,%0;" : "+l"(acc[i][2]) : "l"(hh), "l"(b2));
                asm("fma.rn.f32x2 %0,%1,%2,%0;" : "+l"(acc[i][3]) : "l"(hh), "l"(b3));
            }
        }
        __syncthreads();
    }

    #pragma unroll
    for (int i = 0; i < 8; ++i) {
        int col = mblk + mx * 8 + i;
        float bsum = bih[col] + bhh[col];
        float f[8];
        #pragma unroll
        for (int j = 0; j < 4; ++j)
            asm("mov.b64 {%0,%1},%2;" : "=f"(f[2*j]), "=f"(f[2*j+1]) : "l"(acc[i][j]));
        float* dst = g_G + (size_t)col * 32768 + rblk + nx * 8;
        float4 v0 = make_float4(f[0]+bsum, f[1]+bsum, f[2]+bsum, f[3]+bsum);
        float4 v1 = make_float4(f[4]+bsum, f[5]+bsum, f[6]+bsum, f[7]+bsum);
        *(float4*)dst = v0;
        *(float4*)(dst + 4) = v1;
    }
}

// ============================================================
// Persistent recurrent kernel v5: 128 CTAs x 256 threads.
// CTA j owns units u0=4j..4j+3 (16 gate-cols = 4 gates x 4 units).
// Thread = (bh = tid>>7, kr = (tid>>2)&31, cg = tid&3):
//   gate cg, units u0..u0+3, k in [kr*16, kr*16+16), b in [bh*32, bh*32+32).
// WEIGHTS LIVE IN REGISTERS (32 packed f32x2 pairs), loaded once.
// h streams from L2 (__ldcg float4, 4-slot b-pipeline).
// Split-K: 2 shfl-xor rounds -> 8 slices -> red[8][64][18] in SMEM.
// One grid barrier per step; c state in registers.
// ============================================================
__global__ void __launch_bounds__(RECTHR, 1) lstm_recurrent(
    const float* __restrict__ Whh,
    const float* __restrict__ h0,
    const float* __restrict__ c0,
    float* __restrict__ outSeq,   // layer1: [b][t][u]; layer0: null (writes g_H0T)
    float* __restrict__ hfin,
    float* __restrict__ cfin,
    int layer1)
{
    __shared__ __align__(16) float red[8][64][18];   // [s][b][col], col = gate*4+unit

    const int tid = threadIdx.x;
    const int bid = blockIdx.x;
    const int u0  = bid * 4;
    const int bh  = tid >> 7;            // b half
    const int kr  = (tid >> 2) & 31;     // k range index (16 k each)
    const int cg  = tid & 3;             // gate
    const int sIdx = kr >> 2;            // reduce slice 0..7
    const bool writer = ((tid & 12) == 0);   // kr % 4 == 0
    const int bC  = tid & 63;            // cell batch
    const int uu  = tid >> 6;            // cell unit offset

    // ---- load persistent weights into registers (packed unit-pairs) ----
    // wq[k*2+p] = { Whh[cg*512+u0+2p][kr*16+k], Whh[cg*512+u0+2p+1][kr*16+k] }
    unsigned long long wq[32];
    {
        const float* w0 = Whh + (size_t)(cg * 512 + u0) * 512 + kr * 16;
        const float* w1 = w0 + 512;
        const float* w2 = w1 + 512;
        const float* w3 = w2 + 512;
        #pragma unroll
        for (int k = 0; k < 16; ++k) {
            float a0 = w0[k], a1 = w1[k], a2 = w2[k], a3 = w3[k];
            asm("mov.b64 %0,{%1,%2};" : "=l"(wq[k*2+0]) : "f"(a0), "f"(a1));
            asm("mov.b64 %0,{%1,%2};" : "=l"(wq[k*2+1]) : "f"(a2), "f"(a3));
        }
    }

    // init state
    {
        int idx = bid * RECTHR + tid;
        __stcg(&g_h[idx], h0[idx]);
    }
    float c_reg = c0[bC * HH + u0 + uu];

    gridBarrier();

    for (int t = 0; t < TT; ++t) {
        const float* hRead = g_h + (t & 1) * 32768;
        float* hWrite      = g_h + ((t + 1) & 1) * 32768;
        // float4 base for (b = bh*32 + bl): idx = (bh*32+bl)*128 + kr*4
        const float4* hb = (const float4*)hRead + (bh * 32) * 128 + kr * 4;

        float4 A[4], B[4], C[4], D[4];

        #define LDC(dst, bl) do {                                   \
            const float4* _p = hb + (bl) * 128;                     \
            dst[0] = __ldcg(_p);     dst[1] = __ldcg(_p + 1);       \
            dst[2] = __ldcg(_p + 2); dst[3] = __ldcg(_p + 3);       \
        } while (0)

        #define COMP(buf, bl) do {                                              \
            unsigned long long _a0 = 0ull, _a1 = 0ull;                          \
            _Pragma("unroll")                                                   \
            for (int _j = 0; _j < 4; ++_j) {                                    \
                float4 _hv = buf[_j];                                           \
                _Pragma("unroll")                                               \
                for (int _kk = 0; _kk < 4; ++_kk) {                             \
                    float _h = (&_hv.x)[_kk];                                   \
                    unsigned long long _hh;                                     \
                    asm("mov.b64 %0,{%1,%2};" : "=l"(_hh) : "f"(_h), "f"(_h));  \
                    asm("fma.rn.f32x2 %0,%1,%2,%0;"                             \
                        : "+l"(_a0) : "l"(_hh), "l"(wq[(_j*4+_kk)*2+0]));       \
                    asm("fma.rn.f32x2 %0,%1,%2,%0;"                             \
                        : "+l"(_a1) : "l"(_hh), "l"(wq[(_j*4+_kk)*2+1]));       \
                }                                                               \
            }                                                                   \
            float _s0, _s1, _s2, _s3;                                           \
            asm("mov.b64 {%0,%1},%2;" : "=f"(_s0), "=f"(_s1) : "l"(_a0));       \
            asm("mov.b64 {%0,%1},%2;" : "=f"(_s2), "=f"(_s3) : "l"(_a1));       \
            _s0 += __shfl_xor_sync(0xffffffffu, _s0, 4);                        \
            _s1 += __shfl_xor_sync(0xffffffffu, _s1, 4);                        \
            _s2 += __shfl_xor_sync(0xffffffffu, _s2, 4);                        \
            _s3 += __shfl_xor_sync(0xffffffffu, _s3, 4);                        \
            _s0 += __shfl_xor_sync(0xffffffffu, _s0, 8);                        \
            _s1 += __shfl_xor_sync(0xffffffffu, _s1, 8);                        \
            _s2 += __shfl_xor_sync(0xffffffffu, _s2, 8);                        \
            _s3 += __shfl_xor_sync(0xffffffffu, _s3, 8);                        \
            if (writer) {                                                       \
                float* _r = &red[sIdx][bh * 32 + (bl)][cg * 4];                 \
                *(float2*)_r       = make_float2(_s0, _s1);                     \
                *(float2*)(_r + 2) = make_float2(_s2, _s3);                     \
            }                                                                   \
        } while (0)

        LDC(A, 0); LDC(B, 1);
        for (int bl = 0; bl < 32; bl += 4) {
            LDC(C, bl + 2); LDC(D, bl + 3);
            COMP(A, bl);
            COMP(B, bl + 1);
            if (bl + 4 < 32) { LDC(A, bl + 4); LDC(B, bl + 5); }
            COMP(C, bl + 2);
            COMP(D, bl + 3);
        }
        #undef LDC
        #undef COMP

        __syncthreads();

        // ---- cell update (thread owns (bC, u0+uu); c in register) ----
        {
            float sg[4];
            #pragma unroll
            for (int g = 0; g < 4; ++g) {
                float v = __ldcs(g_G + (size_t)(g * 512 + u0 + uu) * 32768
                                     + (size_t)t * 64 + bC);
                #pragma unroll
                for (int s = 0; s < 8; ++s)
                    v += red[s][bC][g * 4 + uu];
                sg[g] = v;
            }
            float iv = sigmoidf_(sg[0]);
            float fv = sigmoidf_(sg[1]);
            float gv = tanhf(sg[2]);
            float ov = sigmoidf_(sg[3]);
            c_reg = fv * c_reg + iv * gv;
            float hv = ov * tanhf(c_reg);

            __stcg(&hWrite[bC * HH + u0 + uu], hv);
            if (layer1) outSeq[((size_t)bC * TT + t) * HH + u0 + uu] = hv;
            else        __stcg(&g_H0T[(size_t)(u0 + uu) * 32768 + (size_t)t * 64 + bC], hv);
            if (t == TT - 1) {
                hfin[bC * HH + u0 + uu] = hv;
                cfin[bC * HH + u0 + uu] = c_reg;
            }
        }
        gridBarrier();
    }
}

// ============================================================
// kernel_launch: 4 graph-capturable launches.
// Output: out [B,T,H] ++ h_fin [2,B,H] ++ c_fin [2,B,H]
// ============================================================
extern "C" void kernel_launch(void* const* d_in, const int* in_sizes, int n_in,
                              void* d_out, int out_size)
{
    (void)in_sizes; (void)n_in; (void)out_size;
    const float* x   = (const float*)d_in[0];
    const float* h0  = (const float*)d_in[1];
    const float* c0  = (const float*)d_in[2];
    const float* Wih = (const float*)d_in[3];
    const float* Whh = (const float*)d_in[4];
    const float* bih = (const float*)d_in[5];
    const float* bhh = (const float*)d_in[6];
    float* out  = (float*)d_out;
    float* hfin = out + (size_t)BB * TT * HH;
    float* cfin = hfin + 2 * BB * HH;

    dim3 pgrid(32768 / 128, GG / 128);   // (256, 16)

    // layer 0
    lstm_pregemm<<<pgrid, 256>>>(x, Wih, bih, bhh, 1);
    lstm_recurrent<<<RECBLK, RECTHR>>>(Whh, h0, c0, nullptr, hfin, cfin, 0);
    // layer 1 (input GEMM reads g_H0T directly)
    lstm_pregemm<<<pgrid, 256>>>(x, Wih + (size_t)GG * 512, bih + GG, bhh + GG, 0);
    lstm_recurrent<<<RECBLK, RECTHR>>>(Whh + (size_t)GG * 512,
                                       h0 + BB * HH, c0 + BB * HH,
                                       out, hfin + BB * HH, cfin + BB * HH, 1);
}